// round 13
// baseline (speedup 1.0000x reference)
#include <cuda_runtime.h>
#include <cuda_fp16.h>
#include <cstdint>

#define N_TOT  262144
#define E_DIM  512
#define H_DIM  256
#define B_BAGS 512

// ---- scratch (__device__ globals; no runtime allocs) ----
__device__ float g_alpha[N_TOT];
__device__ float g_y[N_TOT * 2];
__device__ int   g_start[B_BAGS + 1];
__device__ __align__(16) __half g_Bf16[H_DIM * E_DIM];  // pre-swizzled per-64-col chunk

// =====================================================================
// helpers (plain sm_103-target PTX: ldmatrix / mma.sync / cp.async)
// =====================================================================
__device__ __forceinline__ uint32_t smem_u32(const void* p) {
    uint32_t a;
    asm("{ .reg .u64 t; cvta.to.shared.u64 t, %1; cvt.u32.u64 %0, t; }" : "=r"(a) : "l"(p));
    return a;
}
__device__ __forceinline__ void ldsm4(uint32_t* r, uint32_t a) {
    asm volatile("ldmatrix.sync.aligned.m8n8.x4.shared.b16 {%0,%1,%2,%3}, [%4];"
                 : "=r"(r[0]), "=r"(r[1]), "=r"(r[2]), "=r"(r[3]) : "r"(a));
}
// fp16-accumulate HMMA: D,C are 2x f16x2 regs. (Rate probe for sm_103a.)
__device__ __forceinline__ void mma_f16h(uint32_t* c, const uint32_t* a, const uint32_t* b) {
    asm volatile(
        "mma.sync.aligned.m16n8k16.row.col.f16.f16.f16.f16 "
        "{%0,%1},{%2,%3,%4,%5},{%6,%7},{%0,%1};"
        : "+r"(c[0]), "+r"(c[1])
        : "r"(a[0]), "r"(a[1]), "r"(a[2]), "r"(a[3]), "r"(b[0]), "r"(b[1]));
}
__device__ __forceinline__ void cp16(uint32_t dst, const void* src) {
    asm volatile("cp.async.cg.shared.global [%0], [%1], 16;" :: "r"(dst), "l"(src));
}
__device__ __forceinline__ void cp_wait_all() {
    asm volatile("cp.async.wait_all;" ::: "memory");
}
__device__ __forceinline__ void cp_commit() {
    asm volatile("cp.async.commit_group;" ::: "memory");
}
__device__ __forceinline__ float tanh_fast(float x) {
    float y; asm("tanh.approx.f32 %0, %1;" : "=f"(y) : "f"(x)); return y;
}
__device__ __forceinline__ uint32_t sw128(uint32_t o) { return o ^ ((o >> 3) & 0x70); }
__device__ __forceinline__ uint32_t cvt_f16x2(float hi, float lo) {
    uint32_t r; asm("cvt.rn.f16x2.f32 %0, %1, %2;" : "=r"(r) : "f"(hi), "f"(lo)); return r;
}

// =====================================================================
// K_pre: fused (a) Vw fp32->fp16 pre-swizzle, (b) bag start offsets.
// =====================================================================
__global__ void k_pre(const int* __restrict__ bi, const float* __restrict__ Vw) {
    int t = blockIdx.x * 256 + threadIdx.x;

    if (t < H_DIM * E_DIM) {          // Vw split: 131072 elems
        int row = t >> 9;             // h
        int k   = t & 511;            // e
        float v = Vw[t];
        int chunk = k >> 6, col = k & 63;
        uint32_t off = (uint32_t)chunk * 32768u + sw128((uint32_t)(row * 128 + col * 2));
        g_Bf16[off >> 1] = __float2half_rn(v);
    }

    if (t < N_TOT) {                  // bag offsets from sorted bi
        int b = bi[t];
        if (t == 0) {
            for (int x = 0; x <= b; ++x) g_start[x] = 0;
        } else {
            int p = bi[t - 1];
            if (p != b) for (int x = p + 1; x <= b; ++x) g_start[x] = t;
        }
        if (t == N_TOT - 1) for (int x = b + 1; x <= B_BAGS; ++x) g_start[x] = N_TOT;
    }
}

// =====================================================================
// K1: fp16 HMMA with fp16 ACCUMULATE (per-chunk) + fp32 master promote.
// CTA tile 64 x 256, K=512 in 8 chunks of 64, double-buffered, 2 CTAs/SM.
// Structure otherwise identical to the measured 276.9us kernel
// (unconditional cp_wait+barrier each iteration; st_A after MMA phase).
// =====================================================================
#define BUF_STRIDE 40960          /* 8KB A + 32KB B per buffer */
#define OFF_A   0
#define OFF_B   8192
#define OFF_WW  81920
#define OFF_VB  82944
#define OFF_DW  83968
#define OFF_RED 88064
#define SMEM_TOTAL 89088

__global__ __launch_bounds__(256, 2) void k_scores_mma(
    const float* __restrict__ X, const float* __restrict__ ww,
    const float* __restrict__ Vb, const float* __restrict__ wbp,
    const float* __restrict__ dw)
{
    extern __shared__ char smem[];
    const uint32_t sb = smem_u32(smem);
    const int tid = threadIdx.x, wid = tid >> 5, l = tid & 31;
    const int wm = wid & 1, wn = wid >> 1;

    float* wwS = (float*)(smem + OFF_WW);
    float* VbS = (float*)(smem + OFF_VB);
    float* dwS = (float*)(smem + OFF_DW);
    wwS[tid] = __ldg(ww + tid);
    VbS[tid] = __ldg(Vb + tid);
#pragma unroll
    for (int i = 0; i < 4; ++i) dwS[tid + i * 256] = __ldg(dw + tid + i * 256);
    __syncthreads();

    const int row0 = blockIdx.x * 64;
    const int lrow = tid >> 2, quad = tid & 3;   // 64 rows, 4 threads/row
    const float* xrow = X + (size_t)(row0 + lrow) * E_DIM + quad * 16;

    float C[2][8][4];            // fp32 master accumulators
    uint32_t Ch[2][8][2];        // per-chunk fp16x2 accumulators
#pragma unroll
    for (int a = 0; a < 2; ++a)
#pragma unroll
        for (int b = 0; b < 8; ++b) {
#pragma unroll
            for (int k = 0; k < 4; ++k) C[a][b][k] = 0.f;
            Ch[a][b][0] = 0u; Ch[a][b][1] = 0u;
        }
    float y0 = 0.f, y1 = 0.f;

    // ldmatrix per-thread address components (bytes, within a 64-col chunk)
    const uint32_t rbA = (uint32_t)((wm * 32 + (l & 15)) * 128);
    const uint32_t ksA = (l & 16) ? 16u : 0u;
    const uint32_t rbB = (uint32_t)((wn * 64 + ((l >> 4) << 3) + (l & 7)) * 128);
    const uint32_t ksB = (l & 8) ? 16u : 0u;

    // ---- B chunk via cp.async (32KB, 8 x 16B per thread) ----
    auto cp_B = [&](int c, int buf) {
        uint32_t db_ = sb + buf * BUF_STRIDE + OFF_B + tid * 16;
        const uint4* gb = ((const uint4*)g_Bf16) + c * 2048 + tid;
#pragma unroll
        for (int i = 0; i < 8; ++i) cp16(db_ + i * 4096, gb + i * 256);
        cp_commit();
    };
    // ---- A: LDG chunk (64x64) into regs: 16 floats/thread ----
    auto ld_A = [&](int c, float4* xv) {
        const float* xp = xrow + c * 64;
#pragma unroll
        for (int j = 0; j < 4; ++j) xv[j] = *(const float4*)(xp + j * 4);
    };
    // ---- A: cvt + swizzled STS + fused dw dots ----
    auto st_A = [&](int c, int buf, const float4* xv) {
        char* aP = smem + buf * BUF_STRIDE + OFF_A;
#pragma unroll
        for (int j = 0; j < 4; ++j) {
            const int colk = quad * 16 + j * 4;
            const int colg = c * 64 + colk;
            float4 v  = xv[j];
            float4 d0 = *(const float4*)(dwS + colg);
            float4 d1 = *(const float4*)(dwS + 512 + colg);
            y0 += v.x * d0.x + v.y * d0.y + v.z * d0.z + v.w * d0.w;
            y1 += v.x * d1.x + v.y * d1.y + v.z * d1.z + v.w * d1.w;
            uint32_t h01 = cvt_f16x2(v.y, v.x);
            uint32_t h23 = cvt_f16x2(v.w, v.z);
            uint32_t off = sw128((uint32_t)(lrow * 128 + colk * 2));
            *(uint2*)(aP + off) = make_uint2(h01, h23);
        }
    };

    // ---- prologue: chunk 0 ----
    float4 xv[4];
    ld_A(0, xv);
    cp_B(0, 0);
    st_A(0, 0, xv);
    cp_wait_all();
    __syncthreads();

    for (int c = 0; c < 8; ++c) {
        const int buf = c & 1;
        if (c < 7) { ld_A(c + 1, xv); cp_B(c + 1, buf ^ 1); }

        const uint32_t aP = sb + buf * BUF_STRIDE + OFF_A;
        const uint32_t bP = sb + buf * BUF_STRIDE + OFF_B;
#pragma unroll
        for (int ks = 0; ks < 4; ++ks) {
            uint32_t Ah[2][4], Bf[4][4];
            const uint32_t swA = sw128(rbA + ks * 32 + ksA);
            const uint32_t swB = sw128(rbB + ks * 32 + ksB);
#pragma unroll
            for (int mf = 0; mf < 2; ++mf) ldsm4(Ah[mf], aP + swA + mf * 2048);
#pragma unroll
            for (int g = 0; g < 4; ++g)    ldsm4(Bf[g], bP + swB + g * 2048);
#pragma unroll
            for (int mf = 0; mf < 2; ++mf)
#pragma unroll
                for (int g = 0; g < 4; ++g) {
                    mma_f16h(Ch[mf][2 * g],     Ah[mf], Bf[g]);
                    mma_f16h(Ch[mf][2 * g + 1], Ah[mf], Bf[g] + 2);
                }
        }
        // ---- promote fp16 chunk accumulators into fp32 master, re-zero ----
#pragma unroll
        for (int mf = 0; mf < 2; ++mf)
#pragma unroll
            for (int nf = 0; nf < 8; ++nf) {
                float2 f01 = __half22float2(*(const half2*)&Ch[mf][nf][0]);
                float2 f23 = __half22float2(*(const half2*)&Ch[mf][nf][1]);
                C[mf][nf][0] += f01.x; C[mf][nf][1] += f01.y;
                C[mf][nf][2] += f23.x; C[mf][nf][3] += f23.y;
                Ch[mf][nf][0] = 0u; Ch[mf][nf][1] = 0u;
            }
        if (c < 7) st_A(c + 1, buf ^ 1, xv);   // STS after MMAs: LDG latency hidden
        cp_wait_all();
        __syncthreads();
    }

    // ---- y writeback (quad reduce across the 4 threads of each row) ----
    float o0 = y0, o1 = y1;
    o0 += __shfl_xor_sync(0xffffffffu, o0, 1);
    o0 += __shfl_xor_sync(0xffffffffu, o0, 2);
    o1 += __shfl_xor_sync(0xffffffffu, o1, 1);
    o1 += __shfl_xor_sync(0xffffffffu, o1, 2);
    if (quad == 0) {
        *(float2*)(g_y + (size_t)(row0 + lrow) * 2) = make_float2(o0, o1);
    }

    // ---- epilogue: tanh + ww-weighted col sum, cross-warp reduce, exp ----
    float* red = (float*)(smem + OFF_RED);
#pragma unroll
    for (int mf = 0; mf < 2; ++mf) {
        float p0 = 0.f, p1 = 0.f;
#pragma unroll
        for (int nf = 0; nf < 8; ++nf) {
            int h = wn * 64 + nf * 8 + (l & 3) * 2;
            float vb0 = VbS[h], vb1 = VbS[h + 1];
            float w0 = wwS[h],  w1 = wwS[h + 1];
            p0 = fmaf(w0, tanh_fast(C[mf][nf][0] + vb0), p0);
            p0 = fmaf(w1, tanh_fast(C[mf][nf][1] + vb1), p0);
            p1 = fmaf(w0, tanh_fast(C[mf][nf][2] + vb0), p1);
            p1 = fmaf(w1, tanh_fast(C[mf][nf][3] + vb1), p1);
        }
        p0 += __shfl_xor_sync(0xffffffffu, p0, 1);
        p0 += __shfl_xor_sync(0xffffffffu, p0, 2);
        p1 += __shfl_xor_sync(0xffffffffu, p1, 1);
        p1 += __shfl_xor_sync(0xffffffffu, p1, 2);
        if ((l & 3) == 0) {
            int r = wm * 32 + mf * 16 + (l >> 2);
            red[r * 4 + wn] = p0;
            red[(r + 8) * 4 + wn] = p1;
        }
    }
    __syncthreads();
    if (tid < 64) {
        float s = red[tid * 4] + red[tid * 4 + 1] + red[tid * 4 + 2] + red[tid * 4 + 3];
        g_alpha[row0 + tid] = __expf(s + __ldg(wbp));
    }
}

// =====================================================================
// K_final: per-bag segment sums of (alpha, alpha*y) -> logits -> softmax
// =====================================================================
__global__ __launch_bounds__(256) void k_final(const float* __restrict__ dbp,
                                               float* __restrict__ out) {
    int b = blockIdx.x, tid = threadIdx.x;
    int s = g_start[b], e = g_start[b + 1];
    float den = 0.f, L0 = 0.f, L1 = 0.f;
    for (int n = s + tid; n < e; n += 256) {
        float a = g_alpha[n];
        float2 y = *(const float2*)(g_y + (size_t)n * 2);
        den += a; L0 += a * y.x; L1 += a * y.y;
    }
#pragma unroll
    for (int m = 16; m >= 1; m >>= 1) {
        den += __shfl_xor_sync(0xffffffffu, den, m);
        L0  += __shfl_xor_sync(0xffffffffu, L0, m);
        L1  += __shfl_xor_sync(0xffffffffu, L1, m);
    }
    __shared__ float sd[8], s0[8], s1[8];
    if ((tid & 31) == 0) { sd[tid >> 5] = den; s0[tid >> 5] = L0; s1[tid >> 5] = L1; }
    __syncthreads();
    if (tid == 0) {
        float D = 0.f, A = 0.f, B = 0.f;
#pragma unroll
        for (int w = 0; w < 8; ++w) { D += sd[w]; A += s0[w]; B += s1[w]; }
        float inv = (D > 0.f) ? (1.f / D) : 0.f;
        float LA = A * inv + __ldg(dbp);
        float LB = B * inv + __ldg(dbp + 1);
        float mx = fmaxf(LA, LB);
        float e0 = __expf(LA - mx), e1 = __expf(LB - mx);
        float dn = 1.f / (e0 + e1);
        out[b * 2 + 0] = e0 * dn;
        out[b * 2 + 1] = e1 * dn;
    }
}

// =====================================================================
extern "C" void kernel_launch(void* const* d_in, const int* in_sizes, int n_in,
                              void* d_out, int out_size) {
    const float* X  = (const float*)d_in[0];   // [N, E]
    const float* Vw = (const float*)d_in[1];   // [H, E]
    const float* Vb = (const float*)d_in[2];   // [H]
    const float* ww = (const float*)d_in[3];   // [1, H]
    const float* wb = (const float*)d_in[4];   // [1]
    const float* dw = (const float*)d_in[5];   // [2, E]
    const float* db = (const float*)d_in[6];   // [2]
    const int*   bi = (const int*)d_in[7];     // [N]
    float* out = (float*)d_out;                // [B, 2]

    cudaFuncSetAttribute(k_scores_mma, cudaFuncAttributeMaxDynamicSharedMemorySize, SMEM_TOTAL);

    k_pre<<<N_TOT / 256, 256>>>(bi, Vw);
    k_scores_mma<<<N_TOT / 64, 256, SMEM_TOTAL>>>(X, ww, Vb, wb, dw);
    k_final<<<B_BAGS, 256>>>(db, out);
}

// round 14
// speedup vs baseline: 1.3372x; 1.3372x over previous
#include <cuda_runtime.h>
#include <cuda_fp16.h>
#include <cstdint>

#define N_TOT  262144
#define E_DIM  512
#define H_DIM  256
#define B_BAGS 512
#define N_TILES 4096
#define GRID_P  296          /* 2 CTAs/SM x 148 SMs */

// ---- scratch (__device__ globals; no runtime allocs) ----
__device__ float g_alpha[N_TOT];
__device__ float g_y[N_TOT * 2];
__device__ int   g_start[B_BAGS + 1];
__device__ __align__(16) __half g_Bf16[H_DIM * E_DIM];  // pre-swizzled per-64-col chunk

// =====================================================================
// helpers (plain sm_103-target PTX: ldmatrix / mma.sync / cp.async)
// =====================================================================
__device__ __forceinline__ uint32_t smem_u32(const void* p) {
    uint32_t a;
    asm("{ .reg .u64 t; cvta.to.shared.u64 t, %1; cvt.u32.u64 %0, t; }" : "=r"(a) : "l"(p));
    return a;
}
__device__ __forceinline__ void ldsm4(uint32_t* r, uint32_t a) {
    asm volatile("ldmatrix.sync.aligned.m8n8.x4.shared.b16 {%0,%1,%2,%3}, [%4];"
                 : "=r"(r[0]), "=r"(r[1]), "=r"(r[2]), "=r"(r[3]) : "r"(a));
}
__device__ __forceinline__ void mma_f16(float* c, const uint32_t* a, const uint32_t* b) {
    asm volatile(
        "mma.sync.aligned.m16n8k16.row.col.f32.f16.f16.f32 "
        "{%0,%1,%2,%3},{%4,%5,%6,%7},{%8,%9},{%0,%1,%2,%3};"
        : "+f"(c[0]), "+f"(c[1]), "+f"(c[2]), "+f"(c[3])
        : "r"(a[0]), "r"(a[1]), "r"(a[2]), "r"(a[3]), "r"(b[0]), "r"(b[1]));
}
__device__ __forceinline__ void cp16(uint32_t dst, const void* src) {
    asm volatile("cp.async.cg.shared.global [%0], [%1], 16;" :: "r"(dst), "l"(src));
}
__device__ __forceinline__ void cp_wait_all() {
    asm volatile("cp.async.wait_all;" ::: "memory");
}
__device__ __forceinline__ void cp_commit() {
    asm volatile("cp.async.commit_group;" ::: "memory");
}
__device__ __forceinline__ float tanh_fast(float x) {
    float y; asm("tanh.approx.f32 %0, %1;" : "=f"(y) : "f"(x)); return y;
}
__device__ __forceinline__ uint32_t sw128(uint32_t o) { return o ^ ((o >> 3) & 0x70); }
__device__ __forceinline__ uint32_t cvt_f16x2(float hi, float lo) {
    uint32_t r; asm("cvt.rn.f16x2.f32 %0, %1, %2;" : "=r"(r) : "f"(hi), "f"(lo)); return r;
}

// =====================================================================
// K_pre: fused (a) Vw fp32->fp16 pre-swizzle, (b) bag start offsets.
// =====================================================================
__global__ void k_pre(const int* __restrict__ bi, const float* __restrict__ Vw) {
    int t = blockIdx.x * 256 + threadIdx.x;

    if (t < H_DIM * E_DIM) {          // Vw split: 131072 elems
        int row = t >> 9;             // h
        int k   = t & 511;            // e
        float v = Vw[t];
        int chunk = k >> 6, col = k & 63;
        uint32_t off = (uint32_t)chunk * 32768u + sw128((uint32_t)(row * 128 + col * 2));
        g_Bf16[off >> 1] = __float2half_rn(v);
    }

    if (t < N_TOT) {                  // bag offsets from sorted bi
        int b = bi[t];
        if (t == 0) {
            for (int x = 0; x <= b; ++x) g_start[x] = 0;
        } else {
            int p = bi[t - 1];
            if (p != b) for (int x = p + 1; x <= b; ++x) g_start[x] = t;
        }
        if (t == N_TOT - 1) for (int x = b + 1; x <= B_BAGS; ++x) g_start[x] = N_TOT;
    }
}

// =====================================================================
// K1: PERSISTENT single-term fp16 HMMA. 296 CTAs (2/SM), each loops over
// tiles (stride 296). Inner 7-chunk loop identical to the proven 276.9us
// kernel (unconditional barriers); chunk 7 peeled statically and
// prefetches the NEXT tile's chunk 0, so the pipeline never drains.
// =====================================================================
#define BUF_STRIDE 40960          /* 8KB A + 32KB B per buffer */
#define OFF_A   0
#define OFF_B   8192
#define OFF_WW  81920
#define OFF_VB  82944
#define OFF_DW  83968
#define OFF_RED 88064
#define SMEM_TOTAL 89088

__global__ __launch_bounds__(256, 2) void k_scores_mma(
    const float* __restrict__ X, const float* __restrict__ ww,
    const float* __restrict__ Vb, const float* __restrict__ wbp,
    const float* __restrict__ dw)
{
    extern __shared__ char smem[];
    const uint32_t sb = smem_u32(smem);
    const int tid = threadIdx.x, wid = tid >> 5, l = tid & 31;
    const int wm = wid & 1, wn = wid >> 1;

    float* wwS = (float*)(smem + OFF_WW);
    float* VbS = (float*)(smem + OFF_VB);
    float* dwS = (float*)(smem + OFF_DW);
    wwS[tid] = __ldg(ww + tid);
    VbS[tid] = __ldg(Vb + tid);
#pragma unroll
    for (int i = 0; i < 4; ++i) dwS[tid + i * 256] = __ldg(dw + tid + i * 256);
    const float wb0 = __ldg(wbp);
    __syncthreads();

    const int lrow = tid >> 2, quad = tid & 3;   // 64 rows, 4 threads/row

    float C[2][8][4];
#pragma unroll
    for (int a = 0; a < 2; ++a)
#pragma unroll
        for (int b = 0; b < 8; ++b)
#pragma unroll
            for (int k = 0; k < 4; ++k) C[a][b][k] = 0.f;
    float y0c = 0.f, y1c = 0.f;   // current tile dw-dots
    float y0n = 0.f, y1n = 0.f;   // next tile (prefetched chunk 0)

    // ldmatrix per-thread address components (bytes, within a 64-col chunk)
    const uint32_t rbA = (uint32_t)((wm * 32 + (l & 15)) * 128);
    const uint32_t ksA = (l & 16) ? 16u : 0u;
    const uint32_t rbB = (uint32_t)((wn * 64 + ((l >> 4) << 3) + (l & 7)) * 128);
    const uint32_t ksB = (l & 8) ? 16u : 0u;

    // ---- B chunk via cp.async (32KB, 8 x 16B per thread) ----
    auto cp_B = [&](int c, int buf) {
        uint32_t db_ = sb + buf * BUF_STRIDE + OFF_B + tid * 16;
        const uint4* gb = ((const uint4*)g_Bf16) + c * 2048 + tid;
#pragma unroll
        for (int i = 0; i < 8; ++i) cp16(db_ + i * 4096, gb + i * 256);
        cp_commit();
    };
    // ---- A: LDG chunk (64x64) into regs from given row base ----
    auto ld_A = [&](const float* xrw, int c, float4* xv) {
        const float* xp = xrw + c * 64;
#pragma unroll
        for (int j = 0; j < 4; ++j) xv[j] = *(const float4*)(xp + j * 4);
    };
    // ---- A: cvt + swizzled STS + fused dw dots into given accumulators ----
    auto st_A = [&](int c, int buf, const float4* xv, float& ry0, float& ry1) {
        char* aP = smem + buf * BUF_STRIDE + OFF_A;
#pragma unroll
        for (int j = 0; j < 4; ++j) {
            const int colk = quad * 16 + j * 4;
            const int colg = c * 64 + colk;
            float4 v  = xv[j];
            float4 d0 = *(const float4*)(dwS + colg);
            float4 d1 = *(const float4*)(dwS + 512 + colg);
            ry0 += v.x * d0.x + v.y * d0.y + v.z * d0.z + v.w * d0.w;
            ry1 += v.x * d1.x + v.y * d1.y + v.z * d1.z + v.w * d1.w;
            uint32_t h01 = cvt_f16x2(v.y, v.x);
            uint32_t h23 = cvt_f16x2(v.w, v.z);
            uint32_t off = sw128((uint32_t)(lrow * 128 + colk * 2));
            *(uint2*)(aP + off) = make_uint2(h01, h23);
        }
    };
    // ---- one full MMA phase over buffer `buf` ----
    auto mma_phase = [&](int buf) {
        const uint32_t aP = sb + buf * BUF_STRIDE + OFF_A;
        const uint32_t bP = sb + buf * BUF_STRIDE + OFF_B;
#pragma unroll
        for (int ks = 0; ks < 4; ++ks) {
            uint32_t Ah[2][4], Bf[4][4];
            const uint32_t swA = sw128(rbA + ks * 32 + ksA);
            const uint32_t swB = sw128(rbB + ks * 32 + ksB);
#pragma unroll
            for (int mf = 0; mf < 2; ++mf) ldsm4(Ah[mf], aP + swA + mf * 2048);
#pragma unroll
            for (int g = 0; g < 4; ++g)    ldsm4(Bf[g], bP + swB + g * 2048);
#pragma unroll
            for (int mf = 0; mf < 2; ++mf)
#pragma unroll
                for (int g = 0; g < 4; ++g) {
                    mma_f16(C[mf][2 * g],     Ah[mf], Bf[g]);
                    mma_f16(C[mf][2 * g + 1], Ah[mf], Bf[g] + 2);
                }
        }
    };

    // ---- persistent prologue: first tile's chunk 0 ----
    int tile = blockIdx.x;
    const float* xrow = X + ((size_t)tile * 64 + lrow) * E_DIM + quad * 16;
    float4 xv[4];
    ld_A(xrow, 0, xv);
    cp_B(0, 0);
    st_A(0, 0, xv, y0c, y1c);
    cp_wait_all();
    __syncthreads();

    for (; tile < N_TILES; tile += GRID_P) {
        const int ntile = tile + GRID_P;
        const float* xrow_n = X + ((size_t)((ntile < N_TILES) ? ntile : 0) * 64 + lrow) * E_DIM + quad * 16;

        // ---- chunks 0..6: identical structure to the proven kernel ----
        for (int c = 0; c < 7; ++c) {
            const int buf = c & 1;
            ld_A(xrow, c + 1, xv);
            cp_B(c + 1, buf ^ 1);
            mma_phase(buf);
            st_A(c + 1, buf ^ 1, xv, y0c, y1c);
            cp_wait_all();
            __syncthreads();
        }
        // ---- chunk 7 (buf=1): prefetch NEXT tile's chunk 0 into buf 0 ----
        ld_A(xrow_n, 0, xv);
        cp_B(0, 0);
        mma_phase(1);
        st_A(0, 0, xv, y0n, y1n);
        cp_wait_all();
        __syncthreads();

        // ---- per-tile epilogue ----
        const int row0 = tile * 64;
        float o0 = y0c, o1 = y1c;
        o0 += __shfl_xor_sync(0xffffffffu, o0, 1);
        o0 += __shfl_xor_sync(0xffffffffu, o0, 2);
        o1 += __shfl_xor_sync(0xffffffffu, o1, 1);
        o1 += __shfl_xor_sync(0xffffffffu, o1, 2);
        if (quad == 0) {
            *(float2*)(g_y + (size_t)(row0 + lrow) * 2) = make_float2(o0, o1);
        }

        float* red = (float*)(smem + OFF_RED);
#pragma unroll
        for (int mf = 0; mf < 2; ++mf) {
            float p0 = 0.f, p1 = 0.f;
#pragma unroll
            for (int nf = 0; nf < 8; ++nf) {
                int h = wn * 64 + nf * 8 + (l & 3) * 2;
                float vb0 = VbS[h], vb1 = VbS[h + 1];
                float w0 = wwS[h],  w1 = wwS[h + 1];
                p0 = fmaf(w0, tanh_fast(C[mf][nf][0] + vb0), p0);
                p0 = fmaf(w1, tanh_fast(C[mf][nf][1] + vb1), p0);
                p1 = fmaf(w0, tanh_fast(C[mf][nf][2] + vb0), p1);
                p1 = fmaf(w1, tanh_fast(C[mf][nf][3] + vb1), p1);
            }
            p0 += __shfl_xor_sync(0xffffffffu, p0, 1);
            p0 += __shfl_xor_sync(0xffffffffu, p0, 2);
            p1 += __shfl_xor_sync(0xffffffffu, p1, 1);
            p1 += __shfl_xor_sync(0xffffffffu, p1, 2);
            if ((l & 3) == 0) {
                int r = wm * 32 + mf * 16 + (l >> 2);
                red[r * 4 + wn] = p0;
                red[(r + 8) * 4 + wn] = p1;
            }
        }
        __syncthreads();
        if (tid < 64) {
            float s = red[tid * 4] + red[tid * 4 + 1] + red[tid * 4 + 2] + red[tid * 4 + 3];
            g_alpha[row0 + tid] = __expf(s + wb0);
        }
        __syncthreads();   // red[] reuse guard for next tile

        // ---- rotate per-tile state ----
        y0c = y0n; y1c = y1n; y0n = 0.f; y1n = 0.f;
#pragma unroll
        for (int a = 0; a < 2; ++a)
#pragma unroll
            for (int b = 0; b < 8; ++b)
#pragma unroll
                for (int k = 0; k < 4; ++k) C[a][b][k] = 0.f;
        xrow = xrow_n;
    }
}

// =====================================================================
// K_final: per-bag segment sums of (alpha, alpha*y) -> logits -> softmax
// =====================================================================
__global__ __launch_bounds__(256) void k_final(const float* __restrict__ dbp,
                                               float* __restrict__ out) {
    int b = blockIdx.x, tid = threadIdx.x;
    int s = g_start[b], e = g_start[b + 1];
    float den = 0.f, L0 = 0.f, L1 = 0.f;
    for (int n = s + tid; n < e; n += 256) {
        float a = g_alpha[n];
        float2 y = *(const float2*)(g_y + (size_t)n * 2);
        den += a; L0 += a * y.x; L1 += a * y.y;
    }
#pragma unroll
    for (int m = 16; m >= 1; m >>= 1) {
        den += __shfl_xor_sync(0xffffffffu, den, m);
        L0  += __shfl_xor_sync(0xffffffffu, L0, m);
        L1  += __shfl_xor_sync(0xffffffffu, L1, m);
    }
    __shared__ float sd[8], s0[8], s1[8];
    if ((tid & 31) == 0) { sd[tid >> 5] = den; s0[tid >> 5] = L0; s1[tid >> 5] = L1; }
    __syncthreads();
    if (tid == 0) {
        float D = 0.f, A = 0.f, B = 0.f;
#pragma unroll
        for (int w = 0; w < 8; ++w) { D += sd[w]; A += s0[w]; B += s1[w]; }
        float inv = (D > 0.f) ? (1.f / D) : 0.f;
        float LA = A * inv + __ldg(dbp);
        float LB = B * inv + __ldg(dbp + 1);
        float mx = fmaxf(LA, LB);
        float e0 = __expf(LA - mx), e1 = __expf(LB - mx);
        float dn = 1.f / (e0 + e1);
        out[b * 2 + 0] = e0 * dn;
        out[b * 2 + 1] = e1 * dn;
    }
}

// =====================================================================
extern "C" void kernel_launch(void* const* d_in, const int* in_sizes, int n_in,
                              void* d_out, int out_size) {
    const float* X  = (const float*)d_in[0];   // [N, E]
    const float* Vw = (const float*)d_in[1];   // [H, E]
    const float* Vb = (const float*)d_in[2];   // [H]
    const float* ww = (const float*)d_in[3];   // [1, H]
    const float* wb = (const float*)d_in[4];   // [1]
    const float* dw = (const float*)d_in[5];   // [2, E]
    const float* db = (const float*)d_in[6];   // [2]
    const int*   bi = (const int*)d_in[7];     // [N]
    float* out = (float*)d_out;                // [B, 2]

    cudaFuncSetAttribute(k_scores_mma, cudaFuncAttributeMaxDynamicSharedMemorySize, SMEM_TOTAL);

    k_pre<<<N_TOT / 256, 256>>>(bi, Vw);
    k_scores_mma<<<GRID_P, 256, SMEM_TOTAL>>>(X, ww, Vb, wb, dw);
    k_final<<<B_BAGS, 256>>>(db, out);
}

// round 15
// speedup vs baseline: 1.3905x; 1.0399x over previous
#include <cuda_runtime.h>
#include <cuda_fp16.h>
#include <cstdint>

#define N_TOT  262144
#define E_DIM  512
#define H_DIM  256
#define B_BAGS 512

// ---- scratch (__device__ globals; no runtime allocs) ----
__device__ float g_alpha[N_TOT];
__device__ float g_y[N_TOT * 2];
__device__ int   g_start[B_BAGS + 1];
__device__ __align__(16) __half g_Bf16[H_DIM * E_DIM];  // pre-swizzled per-64-col chunk

// =====================================================================
// helpers (plain sm_103-target PTX: ldmatrix / mma.sync / cp.async)
// =====================================================================
__device__ __forceinline__ uint32_t smem_u32(const void* p) {
    uint32_t a;
    asm("{ .reg .u64 t; cvta.to.shared.u64 t, %1; cvt.u32.u64 %0, t; }" : "=r"(a) : "l"(p));
    return a;
}
__device__ __forceinline__ void ldsm4(uint32_t* r, uint32_t a) {
    asm volatile("ldmatrix.sync.aligned.m8n8.x4.shared.b16 {%0,%1,%2,%3}, [%4];"
                 : "=r"(r[0]), "=r"(r[1]), "=r"(r[2]), "=r"(r[3]) : "r"(a));
}
__device__ __forceinline__ void mma_f16(float* c, const uint32_t* a, const uint32_t* b) {
    asm volatile(
        "mma.sync.aligned.m16n8k16.row.col.f32.f16.f16.f32 "
        "{%0,%1,%2,%3},{%4,%5,%6,%7},{%8,%9},{%0,%1,%2,%3};"
        : "+f"(c[0]), "+f"(c[1]), "+f"(c[2]), "+f"(c[3])
        : "r"(a[0]), "r"(a[1]), "r"(a[2]), "r"(a[3]), "r"(b[0]), "r"(b[1]));
}
__device__ __forceinline__ void cp16(uint32_t dst, const void* src) {
    asm volatile("cp.async.cg.shared.global [%0], [%1], 16;" :: "r"(dst), "l"(src));
}
__device__ __forceinline__ void cp_wait_all() {
    asm volatile("cp.async.wait_all;" ::: "memory");
}
__device__ __forceinline__ void cp_commit() {
    asm volatile("cp.async.commit_group;" ::: "memory");
}
__device__ __forceinline__ float tanh_fast(float x) {
    float y; asm("tanh.approx.f32 %0, %1;" : "=f"(y) : "f"(x)); return y;
}
__device__ __forceinline__ uint32_t sw128(uint32_t o) { return o ^ ((o >> 3) & 0x70); }
__device__ __forceinline__ uint32_t cvt_f16x2(float hi, float lo) {
    uint32_t r; asm("cvt.rn.f16x2.f32 %0, %1, %2;" : "=r"(r) : "f"(hi), "f"(lo)); return r;
}

// =====================================================================
// K_pre: fused (a) Vw fp32->fp16 pre-swizzle, (b) bag start offsets.
// =====================================================================
__global__ void k_pre(const int* __restrict__ bi, const float* __restrict__ Vw) {
    int t = blockIdx.x * 256 + threadIdx.x;

    if (t < H_DIM * E_DIM) {          // Vw split: 131072 elems
        int row = t >> 9;             // h
        int k   = t & 511;            // e
        float v = Vw[t];
        int chunk = k >> 6, col = k & 63;
        uint32_t off = (uint32_t)chunk * 32768u + sw128((uint32_t)(row * 128 + col * 2));
        g_Bf16[off >> 1] = __float2half_rn(v);
    }

    if (t < N_TOT) {                  // bag offsets from sorted bi
        int b = bi[t];
        if (t == 0) {
            for (int x = 0; x <= b; ++x) g_start[x] = 0;
        } else {
            int p = bi[t - 1];
            if (p != b) for (int x = p + 1; x <= b; ++x) g_start[x] = t;
        }
        if (t == N_TOT - 1) for (int x = b + 1; x <= B_BAGS; ++x) g_start[x] = N_TOT;
    }
}

// =====================================================================
// K1: single-term fp16 HMMA, CTA tile 64 x 256, K=512 in 8 chunks of 64,
// double-buffered, 2 CTAs/SM. Baseline 276.9us structure with the LAST
// CHUNK STATICALLY PEELED: loop c=0..6 has a fully unconditional body
// (no branches, unconditional barrier); chunk 7's MMA phase runs after
// the loop with no dead cp_wait/barrier.
// =====================================================================
#define BUF_STRIDE 40960          /* 8KB A + 32KB B per buffer */
#define OFF_A   0
#define OFF_B   8192
#define OFF_WW  81920
#define OFF_VB  82944
#define OFF_DW  83968
#define OFF_RED 88064
#define SMEM_TOTAL 89088

__global__ __launch_bounds__(256, 2) void k_scores_mma(
    const float* __restrict__ X, const float* __restrict__ ww,
    const float* __restrict__ Vb, const float* __restrict__ wbp,
    const float* __restrict__ dw)
{
    extern __shared__ char smem[];
    const uint32_t sb = smem_u32(smem);
    const int tid = threadIdx.x, wid = tid >> 5, l = tid & 31;
    const int wm = wid & 1, wn = wid >> 1;

    float* wwS = (float*)(smem + OFF_WW);
    float* VbS = (float*)(smem + OFF_VB);
    float* dwS = (float*)(smem + OFF_DW);
    wwS[tid] = __ldg(ww + tid);
    VbS[tid] = __ldg(Vb + tid);
#pragma unroll
    for (int i = 0; i < 4; ++i) dwS[tid + i * 256] = __ldg(dw + tid + i * 256);
    __syncthreads();

    const int row0 = blockIdx.x * 64;
    const int lrow = tid >> 2, quad = tid & 3;   // 64 rows, 4 threads/row
    const float* xrow = X + (size_t)(row0 + lrow) * E_DIM + quad * 16;

    float C[2][8][4];
#pragma unroll
    for (int a = 0; a < 2; ++a)
#pragma unroll
        for (int b = 0; b < 8; ++b)
#pragma unroll
            for (int k = 0; k < 4; ++k) C[a][b][k] = 0.f;
    float y0 = 0.f, y1 = 0.f;

    // ldmatrix per-thread address components (bytes, within a 64-col chunk)
    const uint32_t rbA = (uint32_t)((wm * 32 + (l & 15)) * 128);
    const uint32_t ksA = (l & 16) ? 16u : 0u;
    const uint32_t rbB = (uint32_t)((wn * 64 + ((l >> 4) << 3) + (l & 7)) * 128);
    const uint32_t ksB = (l & 8) ? 16u : 0u;

    // ---- B chunk via cp.async (32KB, 8 x 16B per thread) ----
    auto cp_B = [&](int c, int buf) {
        uint32_t db_ = sb + buf * BUF_STRIDE + OFF_B + tid * 16;
        const uint4* gb = ((const uint4*)g_Bf16) + c * 2048 + tid;
#pragma unroll
        for (int i = 0; i < 8; ++i) cp16(db_ + i * 4096, gb + i * 256);
        cp_commit();
    };
    // ---- A: LDG chunk (64x64) into regs: 16 floats/thread ----
    auto ld_A = [&](int c, float4* xv) {
        const float* xp = xrow + c * 64;
#pragma unroll
        for (int j = 0; j < 4; ++j) xv[j] = *(const float4*)(xp + j * 4);
    };
    // ---- A: cvt + swizzled STS + fused dw dots ----
    auto st_A = [&](int c, int buf, const float4* xv) {
        char* aP = smem + buf * BUF_STRIDE + OFF_A;
#pragma unroll
        for (int j = 0; j < 4; ++j) {
            const int colk = quad * 16 + j * 4;
            const int colg = c * 64 + colk;
            float4 v  = xv[j];
            float4 d0 = *(const float4*)(dwS + colg);
            float4 d1 = *(const float4*)(dwS + 512 + colg);
            y0 += v.x * d0.x + v.y * d0.y + v.z * d0.z + v.w * d0.w;
            y1 += v.x * d1.x + v.y * d1.y + v.z * d1.z + v.w * d1.w;
            uint32_t h01 = cvt_f16x2(v.y, v.x);
            uint32_t h23 = cvt_f16x2(v.w, v.z);
            uint32_t off = sw128((uint32_t)(lrow * 128 + colk * 2));
            *(uint2*)(aP + off) = make_uint2(h01, h23);
        }
    };
    // ---- one full MMA phase over buffer `buf` ----
    auto mma_phase = [&](int buf) {
        const uint32_t aP = sb + buf * BUF_STRIDE + OFF_A;
        const uint32_t bP = sb + buf * BUF_STRIDE + OFF_B;
#pragma unroll
        for (int ks = 0; ks < 4; ++ks) {
            uint32_t Ah[2][4], Bf[4][4];
            const uint32_t swA = sw128(rbA + ks * 32 + ksA);
            const uint32_t swB = sw128(rbB + ks * 32 + ksB);
#pragma unroll
            for (int mf = 0; mf < 2; ++mf) ldsm4(Ah[mf], aP + swA + mf * 2048);
#pragma unroll
            for (int g = 0; g < 4; ++g)    ldsm4(Bf[g], bP + swB + g * 2048);
#pragma unroll
            for (int mf = 0; mf < 2; ++mf)
#pragma unroll
                for (int g = 0; g < 4; ++g) {
                    mma_f16(C[mf][2 * g],     Ah[mf], Bf[g]);
                    mma_f16(C[mf][2 * g + 1], Ah[mf], Bf[g] + 2);
                }
        }
    };

    // ---- prologue: chunk 0 ----
    float4 xv[4];
    ld_A(0, xv);
    cp_B(0, 0);
    st_A(0, 0, xv);
    cp_wait_all();
    __syncthreads();

    // ---- chunks 0..6: fully unconditional body ----
    for (int c = 0; c < 7; ++c) {
        const int buf = c & 1;
        ld_A(c + 1, xv);
        cp_B(c + 1, buf ^ 1);
        mma_phase(buf);
        st_A(c + 1, buf ^ 1, xv);   // STS after MMAs: LDG latency hidden
        cp_wait_all();
        __syncthreads();
    }
    // ---- chunk 7 peeled: no trailing wait/barrier (nothing in flight) ----
    mma_phase(1);

    // ---- y writeback (quad reduce across the 4 threads of each row) ----
    float o0 = y0, o1 = y1;
    o0 += __shfl_xor_sync(0xffffffffu, o0, 1);
    o0 += __shfl_xor_sync(0xffffffffu, o0, 2);
    o1 += __shfl_xor_sync(0xffffffffu, o1, 1);
    o1 += __shfl_xor_sync(0xffffffffu, o1, 2);
    if (quad == 0) {
        *(float2*)(g_y + (size_t)(row0 + lrow) * 2) = make_float2(o0, o1);
    }

    // ---- epilogue: tanh + ww-weighted col sum, cross-warp reduce, exp ----
    float* red = (float*)(smem + OFF_RED);
#pragma unroll
    for (int mf = 0; mf < 2; ++mf) {
        float p0 = 0.f, p1 = 0.f;
#pragma unroll
        for (int nf = 0; nf < 8; ++nf) {
            int h = wn * 64 + nf * 8 + (l & 3) * 2;
            float vb0 = VbS[h], vb1 = VbS[h + 1];
            float w0 = wwS[h],  w1 = wwS[h + 1];
            p0 = fmaf(w0, tanh_fast(C[mf][nf][0] + vb0), p0);
            p0 = fmaf(w1, tanh_fast(C[mf][nf][1] + vb1), p0);
            p1 = fmaf(w0, tanh_fast(C[mf][nf][2] + vb0), p1);
            p1 = fmaf(w1, tanh_fast(C[mf][nf][3] + vb1), p1);
        }
        p0 += __shfl_xor_sync(0xffffffffu, p0, 1);
        p0 += __shfl_xor_sync(0xffffffffu, p0, 2);
        p1 += __shfl_xor_sync(0xffffffffu, p1, 1);
        p1 += __shfl_xor_sync(0xffffffffu, p1, 2);
        if ((l & 3) == 0) {
            int r = wm * 32 + mf * 16 + (l >> 2);
            red[r * 4 + wn] = p0;
            red[(r + 8) * 4 + wn] = p1;
        }
    }
    __syncthreads();
    if (tid < 64) {
        float s = red[tid * 4] + red[tid * 4 + 1] + red[tid * 4 + 2] + red[tid * 4 + 3];
        g_alpha[row0 + tid] = __expf(s + __ldg(wbp));
    }
}

// =====================================================================
// K_final: per-bag segment sums of (alpha, alpha*y) -> logits -> softmax
// =====================================================================
__global__ __launch_bounds__(256) void k_final(const float* __restrict__ dbp,
                                               float* __restrict__ out) {
    int b = blockIdx.x, tid = threadIdx.x;
    int s = g_start[b], e = g_start[b + 1];
    float den = 0.f, L0 = 0.f, L1 = 0.f;
    for (int n = s + tid; n < e; n += 256) {
        float a = g_alpha[n];
        float2 y = *(const float2*)(g_y + (size_t)n * 2);
        den += a; L0 += a * y.x; L1 += a * y.y;
    }
#pragma unroll
    for (int m = 16; m >= 1; m >>= 1) {
        den += __shfl_xor_sync(0xffffffffu, den, m);
        L0  += __shfl_xor_sync(0xffffffffu, L0, m);
        L1  += __shfl_xor_sync(0xffffffffu, L1, m);
    }
    __shared__ float sd[8], s0[8], s1[8];
    if ((tid & 31) == 0) { sd[tid >> 5] = den; s0[tid >> 5] = L0; s1[tid >> 5] = L1; }
    __syncthreads();
    if (tid == 0) {
        float D = 0.f, A = 0.f, B = 0.f;
#pragma unroll
        for (int w = 0; w < 8; ++w) { D += sd[w]; A += s0[w]; B += s1[w]; }
        float inv = (D > 0.f) ? (1.f / D) : 0.f;
        float LA = A * inv + __ldg(dbp);
        float LB = B * inv + __ldg(dbp + 1);
        float mx = fmaxf(LA, LB);
        float e0 = __expf(LA - mx), e1 = __expf(LB - mx);
        float dn = 1.f / (e0 + e1);
        out[b * 2 + 0] = e0 * dn;
        out[b * 2 + 1] = e1 * dn;
    }
}

// =====================================================================
extern "C" void kernel_launch(void* const* d_in, const int* in_sizes, int n_in,
                              void* d_out, int out_size) {
    const float* X  = (const float*)d_in[0];   // [N, E]
    const float* Vw = (const float*)d_in[1];   // [H, E]
    const float* Vb = (const float*)d_in[2];   // [H]
    const float* ww = (const float*)d_in[3];   // [1, H]
    const float* wb = (const float*)d_in[4];   // [1]
    const float* dw = (const float*)d_in[5];   // [2, E]
    const float* db = (const float*)d_in[6];   // [2]
    const int*   bi = (const int*)d_in[7];     // [N]
    float* out = (float*)d_out;                // [B, 2]

    cudaFuncSetAttribute(k_scores_mma, cudaFuncAttributeMaxDynamicSharedMemorySize, SMEM_TOTAL);

    k_pre<<<N_TOT / 256, 256>>>(bi, Vw);
    k_scores_mma<<<N_TOT / 64, 256, SMEM_TOTAL>>>(X, ww, Vb, wb, dw);
    k_final<<<B_BAGS, 256>>>(db, out);
}

// round 16
// speedup vs baseline: 1.4229x; 1.0233x over previous
#include <cuda_runtime.h>
#include <cuda_fp16.h>
#include <cstdint>

#define N_TOT  262144
#define E_DIM  512
#define H_DIM  256
#define B_BAGS 512

// ---- scratch (__device__ globals; no runtime allocs) ----
__device__ float g_alpha[N_TOT];
__device__ float g_y[N_TOT * 2];
__device__ int   g_start[B_BAGS + 1];
__device__ __align__(16) __half g_Bf16[H_DIM * E_DIM];  // pre-swizzled per-64-col chunk

// =====================================================================
// helpers (plain sm_103-target PTX: ldmatrix / mma.sync / cp.async)
// =====================================================================
__device__ __forceinline__ uint32_t smem_u32(const void* p) {
    uint32_t a;
    asm("{ .reg .u64 t; cvta.to.shared.u64 t, %1; cvt.u32.u64 %0, t; }" : "=r"(a) : "l"(p));
    return a;
}
__device__ __forceinline__ void ldsm4(uint32_t* r, uint32_t a) {
    asm volatile("ldmatrix.sync.aligned.m8n8.x4.shared.b16 {%0,%1,%2,%3}, [%4];"
                 : "=r"(r[0]), "=r"(r[1]), "=r"(r[2]), "=r"(r[3]) : "r"(a));
}
__device__ __forceinline__ void mma_f16(float* c, const uint32_t* a, const uint32_t* b) {
    asm volatile(
        "mma.sync.aligned.m16n8k16.row.col.f32.f16.f16.f32 "
        "{%0,%1,%2,%3},{%4,%5,%6,%7},{%8,%9},{%0,%1,%2,%3};"
        : "+f"(c[0]), "+f"(c[1]), "+f"(c[2]), "+f"(c[3])
        : "r"(a[0]), "r"(a[1]), "r"(a[2]), "r"(a[3]), "r"(b[0]), "r"(b[1]));
}
__device__ __forceinline__ void cp16(uint32_t dst, const void* src) {
    asm volatile("cp.async.cg.shared.global [%0], [%1], 16;" :: "r"(dst), "l"(src));
}
__device__ __forceinline__ void cp_wait_all() {
    asm volatile("cp.async.wait_all;" ::: "memory");
}
__device__ __forceinline__ void cp_commit() {
    asm volatile("cp.async.commit_group;" ::: "memory");
}
__device__ __forceinline__ float tanh_fast(float x) {
    float y; asm("tanh.approx.f32 %0, %1;" : "=f"(y) : "f"(x)); return y;
}
__device__ __forceinline__ uint32_t sw128(uint32_t o) { return o ^ ((o >> 3) & 0x70); }
__device__ __forceinline__ uint32_t cvt_f16x2(float hi, float lo) {
    uint32_t r; asm("cvt.rn.f16x2.f32 %0, %1, %2;" : "=r"(r) : "f"(hi), "f"(lo)); return r;
}

// =====================================================================
// K_pre: fused (a) Vw fp32->fp16 pre-swizzle, (b) bag start offsets.
// =====================================================================
__global__ void k_pre(const int* __restrict__ bi, const float* __restrict__ Vw) {
    int t = blockIdx.x * 256 + threadIdx.x;

    if (t < H_DIM * E_DIM) {          // Vw split: 131072 elems
        int row = t >> 9;             // h
        int k   = t & 511;            // e
        float v = Vw[t];
        int chunk = k >> 6, col = k & 63;
        uint32_t off = (uint32_t)chunk * 32768u + sw128((uint32_t)(row * 128 + col * 2));
        g_Bf16[off >> 1] = __float2half_rn(v);
    }

    if (t < N_TOT) {                  // bag offsets from sorted bi
        int b = bi[t];
        if (t == 0) {
            for (int x = 0; x <= b; ++x) g_start[x] = 0;
        } else {
            int p = bi[t - 1];
            if (p != b) for (int x = p + 1; x <= b; ++x) g_start[x] = t;
        }
        if (t == N_TOT - 1) for (int x = b + 1; x <= B_BAGS; ++x) g_start[x] = N_TOT;
    }
}

// =====================================================================
// K1: single-term fp16 HMMA, CTA tile 64 x 256, K=512 in 8 chunks of 64,
// double-buffered, 2 CTAs/SM (cross-CTA overlap hides the serial phases).
// EXACT structure of the measured 276.9us kernel: ld_A/cp_B at loop top,
// st_A after MMA phase, cp_wait+barrier UNCONDITIONAL every iteration.
// Single delta vs that source: wb scalar hoisted to a register at start.
// =====================================================================
#define BUF_STRIDE 40960          /* 8KB A + 32KB B per buffer */
#define OFF_A   0
#define OFF_B   8192
#define OFF_WW  81920
#define OFF_VB  82944
#define OFF_DW  83968
#define OFF_RED 88064
#define SMEM_TOTAL 89088

__global__ __launch_bounds__(256, 2) void k_scores_mma(
    const float* __restrict__ X, const float* __restrict__ ww,
    const float* __restrict__ Vb, const float* __restrict__ wbp,
    const float* __restrict__ dw)
{
    extern __shared__ char smem[];
    const uint32_t sb = smem_u32(smem);
    const int tid = threadIdx.x, wid = tid >> 5, l = tid & 31;
    const int wm = wid & 1, wn = wid >> 1;

    float* wwS = (float*)(smem + OFF_WW);
    float* VbS = (float*)(smem + OFF_VB);
    float* dwS = (float*)(smem + OFF_DW);
    wwS[tid] = __ldg(ww + tid);
    VbS[tid] = __ldg(Vb + tid);
#pragma unroll
    for (int i = 0; i < 4; ++i) dwS[tid + i * 256] = __ldg(dw + tid + i * 256);
    const float wb0 = __ldg(wbp);
    __syncthreads();

    const int row0 = blockIdx.x * 64;
    const int lrow = tid >> 2, quad = tid & 3;   // 64 rows, 4 threads/row
    const float* xrow = X + (size_t)(row0 + lrow) * E_DIM + quad * 16;

    float C[2][8][4];
#pragma unroll
    for (int a = 0; a < 2; ++a)
#pragma unroll
        for (int b = 0; b < 8; ++b)
#pragma unroll
            for (int k = 0; k < 4; ++k) C[a][b][k] = 0.f;
    float y0 = 0.f, y1 = 0.f;

    // ldmatrix per-thread address components (bytes, within a 64-col chunk)
    const uint32_t rbA = (uint32_t)((wm * 32 + (l & 15)) * 128);
    const uint32_t ksA = (l & 16) ? 16u : 0u;
    const uint32_t rbB = (uint32_t)((wn * 64 + ((l >> 4) << 3) + (l & 7)) * 128);
    const uint32_t ksB = (l & 8) ? 16u : 0u;

    // ---- B chunk via cp.async (32KB, 8 x 16B per thread) ----
    auto cp_B = [&](int c, int buf) {
        uint32_t db_ = sb + buf * BUF_STRIDE + OFF_B + tid * 16;
        const uint4* gb = ((const uint4*)g_Bf16) + c * 2048 + tid;
#pragma unroll
        for (int i = 0; i < 8; ++i) cp16(db_ + i * 4096, gb + i * 256);
        cp_commit();
    };
    // ---- A: LDG chunk (64x64) into regs: 16 floats/thread ----
    auto ld_A = [&](int c, float4* xv) {
        const float* xp = xrow + c * 64;
#pragma unroll
        for (int j = 0; j < 4; ++j) xv[j] = *(const float4*)(xp + j * 4);
    };
    // ---- A: cvt + swizzled STS + fused dw dots ----
    auto st_A = [&](int c, int buf, const float4* xv) {
        char* aP = smem + buf * BUF_STRIDE + OFF_A;
#pragma unroll
        for (int j = 0; j < 4; ++j) {
            const int colk = quad * 16 + j * 4;
            const int colg = c * 64 + colk;
            float4 v  = xv[j];
            float4 d0 = *(const float4*)(dwS + colg);
            float4 d1 = *(const float4*)(dwS + 512 + colg);
            y0 += v.x * d0.x + v.y * d0.y + v.z * d0.z + v.w * d0.w;
            y1 += v.x * d1.x + v.y * d1.y + v.z * d1.z + v.w * d1.w;
            uint32_t h01 = cvt_f16x2(v.y, v.x);
            uint32_t h23 = cvt_f16x2(v.w, v.z);
            uint32_t off = sw128((uint32_t)(lrow * 128 + colk * 2));
            *(uint2*)(aP + off) = make_uint2(h01, h23);
        }
    };

    // ---- prologue: chunk 0 ----
    float4 xv[4];
    ld_A(0, xv);
    cp_B(0, 0);
    st_A(0, 0, xv);
    cp_wait_all();
    __syncthreads();

    for (int c = 0; c < 8; ++c) {
        const int buf = c & 1;
        if (c < 7) { ld_A(c + 1, xv); cp_B(c + 1, buf ^ 1); }

        const uint32_t aP = sb + buf * BUF_STRIDE + OFF_A;
        const uint32_t bP = sb + buf * BUF_STRIDE + OFF_B;
#pragma unroll
        for (int ks = 0; ks < 4; ++ks) {
            uint32_t Ah[2][4], Bf[4][4];
            const uint32_t swA = sw128(rbA + ks * 32 + ksA);
            const uint32_t swB = sw128(rbB + ks * 32 + ksB);
#pragma unroll
            for (int mf = 0; mf < 2; ++mf) ldsm4(Ah[mf], aP + swA + mf * 2048);
#pragma unroll
            for (int g = 0; g < 4; ++g)    ldsm4(Bf[g], bP + swB + g * 2048);
#pragma unroll
            for (int mf = 0; mf < 2; ++mf)
#pragma unroll
                for (int g = 0; g < 4; ++g) {
                    mma_f16(C[mf][2 * g],     Ah[mf], Bf[g]);
                    mma_f16(C[mf][2 * g + 1], Ah[mf], Bf[g] + 2);
                }
        }
        if (c < 7) st_A(c + 1, buf ^ 1, xv);   // STS after MMAs: LDG latency hidden
        cp_wait_all();
        __syncthreads();
    }

    // ---- y writeback (quad reduce across the 4 threads of each row) ----
    float o0 = y0, o1 = y1;
    o0 += __shfl_xor_sync(0xffffffffu, o0, 1);
    o0 += __shfl_xor_sync(0xffffffffu, o0, 2);
    o1 += __shfl_xor_sync(0xffffffffu, o1, 1);
    o1 += __shfl_xor_sync(0xffffffffu, o1, 2);
    if (quad == 0) {
        *(float2*)(g_y + (size_t)(row0 + lrow) * 2) = make_float2(o0, o1);
    }

    // ---- epilogue: tanh + ww-weighted col sum, cross-warp reduce, exp ----
    float* red = (float*)(smem + OFF_RED);
#pragma unroll
    for (int mf = 0; mf < 2; ++mf) {
        float p0 = 0.f, p1 = 0.f;
#pragma unroll
        for (int nf = 0; nf < 8; ++nf) {
            int h = wn * 64 + nf * 8 + (l & 3) * 2;
            float vb0 = VbS[h], vb1 = VbS[h + 1];
            float w0 = wwS[h],  w1 = wwS[h + 1];
            p0 = fmaf(w0, tanh_fast(C[mf][nf][0] + vb0), p0);
            p0 = fmaf(w1, tanh_fast(C[mf][nf][1] + vb1), p0);
            p1 = fmaf(w0, tanh_fast(C[mf][nf][2] + vb0), p1);
            p1 = fmaf(w1, tanh_fast(C[mf][nf][3] + vb1), p1);
        }
        p0 += __shfl_xor_sync(0xffffffffu, p0, 1);
        p0 += __shfl_xor_sync(0xffffffffu, p0, 2);
        p1 += __shfl_xor_sync(0xffffffffu, p1, 1);
        p1 += __shfl_xor_sync(0xffffffffu, p1, 2);
        if ((l & 3) == 0) {
            int r = wm * 32 + mf * 16 + (l >> 2);
            red[r * 4 + wn] = p0;
            red[(r + 8) * 4 + wn] = p1;
        }
    }
    __syncthreads();
    if (tid < 64) {
        float s = red[tid * 4] + red[tid * 4 + 1] + red[tid * 4 + 2] + red[tid * 4 + 3];
        g_alpha[row0 + tid] = __expf(s + wb0);
    }
}

// =====================================================================
// K_final: per-bag segment sums of (alpha, alpha*y) -> logits -> softmax
// =====================================================================
__global__ __launch_bounds__(256) void k_final(const float* __restrict__ dbp,
                                               float* __restrict__ out) {
    int b = blockIdx.x, tid = threadIdx.x;
    int s = g_start[b], e = g_start[b + 1];
    float den = 0.f, L0 = 0.f, L1 = 0.f;
    for (int n = s + tid; n < e; n += 256) {
        float a = g_alpha[n];
        float2 y = *(const float2*)(g_y + (size_t)n * 2);
        den += a; L0 += a * y.x; L1 += a * y.y;
    }
#pragma unroll
    for (int m = 16; m >= 1; m >>= 1) {
        den += __shfl_xor_sync(0xffffffffu, den, m);
        L0  += __shfl_xor_sync(0xffffffffu, L0, m);
        L1  += __shfl_xor_sync(0xffffffffu, L1, m);
    }
    __shared__ float sd[8], s0[8], s1[8];
    if ((tid & 31) == 0) { sd[tid >> 5] = den; s0[tid >> 5] = L0; s1[tid >> 5] = L1; }
    __syncthreads();
    if (tid == 0) {
        float D = 0.f, A = 0.f, B = 0.f;
#pragma unroll
        for (int w = 0; w < 8; ++w) { D += sd[w]; A += s0[w]; B += s1[w]; }
        float inv = (D > 0.f) ? (1.f / D) : 0.f;
        float LA = A * inv + __ldg(dbp);
        float LB = B * inv + __ldg(dbp + 1);
        float mx = fmaxf(LA, LB);
        float e0 = __expf(LA - mx), e1 = __expf(LB - mx);
        float dn = 1.f / (e0 + e1);
        out[b * 2 + 0] = e0 * dn;
        out[b * 2 + 1] = e1 * dn;
    }
}

// =====================================================================
extern "C" void kernel_launch(void* const* d_in, const int* in_sizes, int n_in,
                              void* d_out, int out_size) {
    const float* X  = (const float*)d_in[0];   // [N, E]
    const float* Vw = (const float*)d_in[1];   // [H, E]
    const float* Vb = (const float*)d_in[2];   // [H]
    const float* ww = (const float*)d_in[3];   // [1, H]
    const float* wb = (const float*)d_in[4];   // [1]
    const float* dw = (const float*)d_in[5];   // [2, E]
    const float* db = (const float*)d_in[6];   // [2]
    const int*   bi = (const int*)d_in[7];     // [N]
    float* out = (float*)d_out;                // [B, 2]

    cudaFuncSetAttribute(k_scores_mma, cudaFuncAttributeMaxDynamicSharedMemorySize, SMEM_TOTAL);

    k_pre<<<N_TOT / 256, 256>>>(bi, Vw);
    k_scores_mma<<<N_TOT / 64, 256, SMEM_TOTAL>>>(X, ww, Vb, wb, dw);
    k_final<<<B_BAGS, 256>>>(db, out);
}

// round 17
// speedup vs baseline: 1.4358x; 1.0090x over previous
#include <cuda_runtime.h>
#include <cuda_fp16.h>
#include <cstdint>

#define N_TOT  262144
#define E_DIM  512
#define H_DIM  256
#define B_BAGS 512

// ---- scratch (__device__ globals; no runtime allocs) ----
__device__ float g_alpha[N_TOT];
__device__ float g_y[N_TOT * 2];
__device__ int   g_start[B_BAGS + 1];
__device__ __align__(16) __half g_Bf16[H_DIM * E_DIM];  // pre-swizzled per-64-col chunk

// =====================================================================
// helpers (plain sm_103-target PTX: ldmatrix / mma.sync / cp.async)
// =====================================================================
__device__ __forceinline__ uint32_t smem_u32(const void* p) {
    uint32_t a;
    asm("{ .reg .u64 t; cvta.to.shared.u64 t, %1; cvt.u32.u64 %0, t; }" : "=r"(a) : "l"(p));
    return a;
}
__device__ __forceinline__ void ldsm4(uint32_t* r, uint32_t a) {
    asm volatile("ldmatrix.sync.aligned.m8n8.x4.shared.b16 {%0,%1,%2,%3}, [%4];"
                 : "=r"(r[0]), "=r"(r[1]), "=r"(r[2]), "=r"(r[3]) : "r"(a));
}
__device__ __forceinline__ void mma_f16(float* c, const uint32_t* a, const uint32_t* b) {
    asm volatile(
        "mma.sync.aligned.m16n8k16.row.col.f32.f16.f16.f32 "
        "{%0,%1,%2,%3},{%4,%5,%6,%7},{%8,%9},{%0,%1,%2,%3};"
        : "+f"(c[0]), "+f"(c[1]), "+f"(c[2]), "+f"(c[3])
        : "r"(a[0]), "r"(a[1]), "r"(a[2]), "r"(a[3]), "r"(b[0]), "r"(b[1]));
}
__device__ __forceinline__ void cp16(uint32_t dst, const void* src) {
    asm volatile("cp.async.cg.shared.global [%0], [%1], 16;" :: "r"(dst), "l"(src));
}
__device__ __forceinline__ void cp_wait_all() {
    asm volatile("cp.async.wait_all;" ::: "memory");
}
__device__ __forceinline__ void cp_commit() {
    asm volatile("cp.async.commit_group;" ::: "memory");
}
__device__ __forceinline__ float tanh_fast(float x) {
    float y; asm("tanh.approx.f32 %0, %1;" : "=f"(y) : "f"(x)); return y;
}
__device__ __forceinline__ uint32_t sw128(uint32_t o) { return o ^ ((o >> 3) & 0x70); }
__device__ __forceinline__ uint32_t cvt_f16x2(float hi, float lo) {
    uint32_t r; asm("cvt.rn.f16x2.f32 %0, %1, %2;" : "=r"(r) : "f"(hi), "f"(lo)); return r;
}
// streaming (evict-first) float4 load: X is read exactly once
__device__ __forceinline__ float4 ldg_cs4(const float* p) {
    float4 v;
    asm volatile("ld.global.cs.v4.f32 {%0,%1,%2,%3}, [%4];"
                 : "=f"(v.x), "=f"(v.y), "=f"(v.z), "=f"(v.w) : "l"(p));
    return v;
}

// =====================================================================
// K_pre: fused (a) Vw fp32->fp16 pre-swizzle, (b) bag start offsets.
// =====================================================================
__global__ void k_pre(const int* __restrict__ bi, const float* __restrict__ Vw) {
    int t = blockIdx.x * 256 + threadIdx.x;

    if (t < H_DIM * E_DIM) {          // Vw split: 131072 elems
        int row = t >> 9;             // h
        int k   = t & 511;            // e
        float v = Vw[t];
        int chunk = k >> 6, col = k & 63;
        uint32_t off = (uint32_t)chunk * 32768u + sw128((uint32_t)(row * 128 + col * 2));
        g_Bf16[off >> 1] = __float2half_rn(v);
    }

    if (t < N_TOT) {                  // bag offsets from sorted bi
        int b = bi[t];
        if (t == 0) {
            for (int x = 0; x <= b; ++x) g_start[x] = 0;
        } else {
            int p = bi[t - 1];
            if (p != b) for (int x = p + 1; x <= b; ++x) g_start[x] = t;
        }
        if (t == N_TOT - 1) for (int x = b + 1; x <= B_BAGS; ++x) g_start[x] = N_TOT;
    }
}

// =====================================================================
// K1: single-term fp16 HMMA, CTA tile 64 x 256, K=512 in 8 chunks of 64,
// double-buffered, 2 CTAs/SM (cross-CTA overlap hides the serial phases).
// EXACT structure of the measured 275.0us kernel. Single delta: X loads
// use ld.global.cs (streaming, evict-first) so the once-read X stream
// does not compete with the hot B working set in L2/L1.
// =====================================================================
#define BUF_STRIDE 40960          /* 8KB A + 32KB B per buffer */
#define OFF_A   0
#define OFF_B   8192
#define OFF_WW  81920
#define OFF_VB  82944
#define OFF_DW  83968
#define OFF_RED 88064
#define SMEM_TOTAL 89088

__global__ __launch_bounds__(256, 2) void k_scores_mma(
    const float* __restrict__ X, const float* __restrict__ ww,
    const float* __restrict__ Vb, const float* __restrict__ wbp,
    const float* __restrict__ dw)
{
    extern __shared__ char smem[];
    const uint32_t sb = smem_u32(smem);
    const int tid = threadIdx.x, wid = tid >> 5, l = tid & 31;
    const int wm = wid & 1, wn = wid >> 1;

    float* wwS = (float*)(smem + OFF_WW);
    float* VbS = (float*)(smem + OFF_VB);
    float* dwS = (float*)(smem + OFF_DW);
    wwS[tid] = __ldg(ww + tid);
    VbS[tid] = __ldg(Vb + tid);
#pragma unroll
    for (int i = 0; i < 4; ++i) dwS[tid + i * 256] = __ldg(dw + tid + i * 256);
    const float wb0 = __ldg(wbp);
    __syncthreads();

    const int row0 = blockIdx.x * 64;
    const int lrow = tid >> 2, quad = tid & 3;   // 64 rows, 4 threads/row
    const float* xrow = X + (size_t)(row0 + lrow) * E_DIM + quad * 16;

    float C[2][8][4];
#pragma unroll
    for (int a = 0; a < 2; ++a)
#pragma unroll
        for (int b = 0; b < 8; ++b)
#pragma unroll
            for (int k = 0; k < 4; ++k) C[a][b][k] = 0.f;
    float y0 = 0.f, y1 = 0.f;

    // ldmatrix per-thread address components (bytes, within a 64-col chunk)
    const uint32_t rbA = (uint32_t)((wm * 32 + (l & 15)) * 128);
    const uint32_t ksA = (l & 16) ? 16u : 0u;
    const uint32_t rbB = (uint32_t)((wn * 64 + ((l >> 4) << 3) + (l & 7)) * 128);
    const uint32_t ksB = (l & 8) ? 16u : 0u;

    // ---- B chunk via cp.async (32KB, 8 x 16B per thread) ----
    auto cp_B = [&](int c, int buf) {
        uint32_t db_ = sb + buf * BUF_STRIDE + OFF_B + tid * 16;
        const uint4* gb = ((const uint4*)g_Bf16) + c * 2048 + tid;
#pragma unroll
        for (int i = 0; i < 8; ++i) cp16(db_ + i * 4096, gb + i * 256);
        cp_commit();
    };
    // ---- A: streaming LDG chunk (64x64) into regs: 16 floats/thread ----
    auto ld_A = [&](int c, float4* xv) {
        const float* xp = xrow + c * 64;
#pragma unroll
        for (int j = 0; j < 4; ++j) xv[j] = ldg_cs4(xp + j * 4);
    };
    // ---- A: cvt + swizzled STS + fused dw dots ----
    auto st_A = [&](int c, int buf, const float4* xv) {
        char* aP = smem + buf * BUF_STRIDE + OFF_A;
#pragma unroll
        for (int j = 0; j < 4; ++j) {
            const int colk = quad * 16 + j * 4;
            const int colg = c * 64 + colk;
            float4 v  = xv[j];
            float4 d0 = *(const float4*)(dwS + colg);
            float4 d1 = *(const float4*)(dwS + 512 + colg);
            y0 += v.x * d0.x + v.y * d0.y + v.z * d0.z + v.w * d0.w;
            y1 += v.x * d1.x + v.y * d1.y + v.z * d1.z + v.w * d1.w;
            uint32_t h01 = cvt_f16x2(v.y, v.x);
            uint32_t h23 = cvt_f16x2(v.w, v.z);
            uint32_t off = sw128((uint32_t)(lrow * 128 + colk * 2));
            *(uint2*)(aP + off) = make_uint2(h01, h23);
        }
    };

    // ---- prologue: chunk 0 ----
    float4 xv[4];
    ld_A(0, xv);
    cp_B(0, 0);
    st_A(0, 0, xv);
    cp_wait_all();
    __syncthreads();

    for (int c = 0; c < 8; ++c) {
        const int buf = c & 1;
        if (c < 7) { ld_A(c + 1, xv); cp_B(c + 1, buf ^ 1); }

        const uint32_t aP = sb + buf * BUF_STRIDE + OFF_A;
        const uint32_t bP = sb + buf * BUF_STRIDE + OFF_B;
#pragma unroll
        for (int ks = 0; ks < 4; ++ks) {
            uint32_t Ah[2][4], Bf[4][4];
            const uint32_t swA = sw128(rbA + ks * 32 + ksA);
            const uint32_t swB = sw128(rbB + ks * 32 + ksB);
#pragma unroll
            for (int mf = 0; mf < 2; ++mf) ldsm4(Ah[mf], aP + swA + mf * 2048);
#pragma unroll
            for (int g = 0; g < 4; ++g)    ldsm4(Bf[g], bP + swB + g * 2048);
#pragma unroll
            for (int mf = 0; mf < 2; ++mf)
#pragma unroll
                for (int g = 0; g < 4; ++g) {
                    mma_f16(C[mf][2 * g],     Ah[mf], Bf[g]);
                    mma_f16(C[mf][2 * g + 1], Ah[mf], Bf[g] + 2);
                }
        }
        if (c < 7) st_A(c + 1, buf ^ 1, xv);   // STS after MMAs: LDG latency hidden
        cp_wait_all();
        __syncthreads();
    }

    // ---- y writeback (quad reduce across the 4 threads of each row) ----
    float o0 = y0, o1 = y1;
    o0 += __shfl_xor_sync(0xffffffffu, o0, 1);
    o0 += __shfl_xor_sync(0xffffffffu, o0, 2);
    o1 += __shfl_xor_sync(0xffffffffu, o1, 1);
    o1 += __shfl_xor_sync(0xffffffffu, o1, 2);
    if (quad == 0) {
        *(float2*)(g_y + (size_t)(row0 + lrow) * 2) = make_float2(o0, o1);
    }

    // ---- epilogue: tanh + ww-weighted col sum, cross-warp reduce, exp ----
    float* red = (float*)(smem + OFF_RED);
#pragma unroll
    for (int mf = 0; mf < 2; ++mf) {
        float p0 = 0.f, p1 = 0.f;
#pragma unroll
        for (int nf = 0; nf < 8; ++nf) {
            int h = wn * 64 + nf * 8 + (l & 3) * 2;
            float vb0 = VbS[h], vb1 = VbS[h + 1];
            float w0 = wwS[h],  w1 = wwS[h + 1];
            p0 = fmaf(w0, tanh_fast(C[mf][nf][0] + vb0), p0);
            p0 = fmaf(w1, tanh_fast(C[mf][nf][1] + vb1), p0);
            p1 = fmaf(w0, tanh_fast(C[mf][nf][2] + vb0), p1);
            p1 = fmaf(w1, tanh_fast(C[mf][nf][3] + vb1), p1);
        }
        p0 += __shfl_xor_sync(0xffffffffu, p0, 1);
        p0 += __shfl_xor_sync(0xffffffffu, p0, 2);
        p1 += __shfl_xor_sync(0xffffffffu, p1, 1);
        p1 += __shfl_xor_sync(0xffffffffu, p1, 2);
        if ((l & 3) == 0) {
            int r = wm * 32 + mf * 16 + (l >> 2);
            red[r * 4 + wn] = p0;
            red[(r + 8) * 4 + wn] = p1;
        }
    }
    __syncthreads();
    if (tid < 64) {
        float s = red[tid * 4] + red[tid * 4 + 1] + red[tid * 4 + 2] + red[tid * 4 + 3];
        g_alpha[row0 + tid] = __expf(s + wb0);
    }
}

// =====================================================================
// K_final: per-bag segment sums of (alpha, alpha*y) -> logits -> softmax
// =====================================================================
__global__ __launch_bounds__(256) void k_final(const float* __restrict__ dbp,
                                               float* __restrict__ out) {
    int b = blockIdx.x, tid = threadIdx.x;
    int s = g_start[b], e = g_start[b + 1];
    float den = 0.f, L0 = 0.f, L1 = 0.f;
    for (int n = s + tid; n < e; n += 256) {
        float a = g_alpha[n];
        float2 y = *(const float2*)(g_y + (size_t)n * 2);
        den += a; L0 += a * y.x; L1 += a * y.y;
    }
#pragma unroll
    for (int m = 16; m >= 1; m >>= 1) {
        den += __shfl_xor_sync(0xffffffffu, den, m);
        L0  += __shfl_xor_sync(0xffffffffu, L0, m);
        L1  += __shfl_xor_sync(0xffffffffu, L1, m);
    }
    __shared__ float sd[8], s0[8], s1[8];
    if ((tid & 31) == 0) { sd[tid >> 5] = den; s0[tid >> 5] = L0; s1[tid >> 5] = L1; }
    __syncthreads();
    if (tid == 0) {
        float D = 0.f, A = 0.f, B = 0.f;
#pragma unroll
        for (int w = 0; w < 8; ++w) { D += sd[w]; A += s0[w]; B += s1[w]; }
        float inv = (D > 0.f) ? (1.f / D) : 0.f;
        float LA = A * inv + __ldg(dbp);
        float LB = B * inv + __ldg(dbp + 1);
        float mx = fmaxf(LA, LB);
        float e0 = __expf(LA - mx), e1 = __expf(LB - mx);
        float dn = 1.f / (e0 + e1);
        out[b * 2 + 0] = e0 * dn;
        out[b * 2 + 1] = e1 * dn;
    }
}

// =====================================================================
extern "C" void kernel_launch(void* const* d_in, const int* in_sizes, int n_in,
                              void* d_out, int out_size) {
    const float* X  = (const float*)d_in[0];   // [N, E]
    const float* Vw = (const float*)d_in[1];   // [H, E]
    const float* Vb = (const float*)d_in[2];   // [H]
    const float* ww = (const float*)d_in[3];   // [1, H]
    const float* wb = (const float*)d_in[4];   // [1]
    const float* dw = (const float*)d_in[5];   // [2, E]
    const float* db = (const float*)d_in[6];   // [2]
    const int*   bi = (const int*)d_in[7];     // [N]
    float* out = (float*)d_out;                // [B, 2]

    cudaFuncSetAttribute(k_scores_mma, cudaFuncAttributeMaxDynamicSharedMemorySize, SMEM_TOTAL);

    k_pre<<<N_TOT / 256, 256>>>(bi, Vw);
    k_scores_mma<<<N_TOT / 64, 256, SMEM_TOTAL>>>(X, ww, Vb, wb, dw);
    k_final<<<B_BAGS, 256>>>(db, out);
}